// round 6
// baseline (speedup 1.0000x reference)
#include <cuda_runtime.h>

#define HH 512
#define WW 512
#define BB 8
#define NPIX (HH*WW)
#define ITERS 50
#define CC 256.5f

// Double-buffered state + triple-buffered moment sums (zero/accum/read rotate).
__device__ float  g_u[2][BB*NPIX];
__device__ float  g_q[2][BB*NPIX];
__device__ double g_sums[3][BB][8];

__global__ void zero_sums_kernel() {
    int i = threadIdx.x;
    if (i < 3*BB*8) reinterpret_cast<double*>(g_sums)[i] = 0.0;
}

// Block-reduce 6 accumulators and fp64-atomicAdd into dst[0..5].
__device__ __forceinline__ void moments_accum_and_atomic(float acc[6], double* dst,
                                                         float (*red)[6]) {
    int tid = threadIdx.y * 32 + threadIdx.x;
#pragma unroll
    for (int off = 16; off; off >>= 1)
#pragma unroll
        for (int k = 0; k < 6; k++) acc[k] += __shfl_xor_sync(0xffffffffu, acc[k], off);
    if (threadIdx.x == 0)
#pragma unroll
        for (int k = 0; k < 6; k++) red[threadIdx.y][k] = acc[k];
    __syncthreads();
    if (tid == 0) {
#pragma unroll
        for (int k = 0; k < 6; k++) {
            float s = red[0][k];
#pragma unroll
            for (int w = 1; w < 8; w++) s += red[w][k];
            atomicAdd(&dst[k], (double)s);
        }
    }
}

// u0 = sigmoid(o), q0 = 0, moments(u0) -> g_sums[0]
__global__ __launch_bounds__(256) void init_kernel(const float* __restrict__ o) {
    int b  = blockIdx.z;
    int i0 = blockIdx.y * 32, j0 = blockIdx.x * 32;
    const float* ob = o      + (size_t)b * NPIX;
    float*       ub = g_u[0] + (size_t)b * NPIX;
    float*       qb = g_q[0] + (size_t)b * NPIX;
    float acc[6] = {0,0,0,0,0,0};
#pragma unroll
    for (int k = 0; k < 4; k++) {
        int i = i0 + threadIdx.y + k*8;
        int j = j0 + threadIdx.x;
        int idx = i*WW + j;
        float u = 1.f/(1.f + __expf(-ob[idx]));
        ub[idx] = u; qb[idx] = 0.f;
        float xc = (float)(i+1) - CC, yc = (float)(j+1) - CC;
        acc[0]+=u; float a1=u*xc, a2=u*yc;
        acc[1]+=a1; acc[2]+=a2; acc[3]+=a1*xc; acc[4]+=a2*yc; acc[5]+=a1*yc;
    }
    __shared__ float red[8][6];
    moments_accum_and_atomic(acc, g_sums[0][b], red);
}

// One full iteration: p (separable 5x5 gauss on u), Tx/Ty field, q update,
// Tq divergence, u update; accumulates next iteration's moments.
__global__ __launch_bounds__(256) void step_kernel(const float* __restrict__ o,
                                                   float* __restrict__ out, int t)
{
    __shared__ float u_s[36][36];     // u tile, halo 2, zero-padded at image border
    __shared__ float t_s[36][32];     // gaussian column pass
    __shared__ float txq_s[34][34];   // Tx * q_new (halo 1)
    __shared__ float tyq_s[34][34];   // Ty * q_new
    __shared__ float qn_s[34][34];    // q_new
    __shared__ float sc[5];
    __shared__ float red[8][6];

    int b  = blockIdx.z;
    int i0 = blockIdx.y * 32, j0 = blockIdx.x * 32;
    int tid = threadIdx.y * 32 + threadIdx.x;

    const float* u_in  = g_u[t & 1]     + (size_t)b * NPIX;
    const float* q_in  = g_q[t & 1]     + (size_t)b * NPIX;
    float*       u_out = g_u[(t+1) & 1] + (size_t)b * NPIX;
    float*       q_out = g_q[(t+1) & 1] + (size_t)b * NPIX;
    const float* ob    = o              + (size_t)b * NPIX;

    // Zero the sums buffer used two iterations from now (safe: last read was t-1).
    if (blockIdx.x == 0 && blockIdx.y == 0 && b == 0 && tid < BB*8)
        reinterpret_cast<double*>(g_sums[(t+2)%3])[tid] = 0.0;

    if (tid == 0) {  // scalars from fp64 moments (centered at CC)
        const double* S = g_sums[t % 3][b];
        double inv = 1.0 / S[0];
        double dx = S[1]*inv, dy = S[2]*inv;
        sc[0] = (float)dx; sc[1] = (float)dy;
        sc[2] = (float)(S[5]*inv - dx*dy);   // cossin
        sc[3] = (float)(S[3]*inv - dx*dx);   // bsin
        sc[4] = (float)(S[4]*inv - dy*dy);   // asin
    }

    // Load u tile with halo 2 (zero pad outside image = conv zero padding).
    for (int idx = tid; idx < 36*36; idx += 256) {
        int r = idx / 36, c = idx - r*36;
        int gi = i0 + r - 2, gj = j0 + c - 2;
        float v = 0.f;
        if ((unsigned)gi < HH && (unsigned)gj < WW) v = u_in[gi*WW + gj];
        u_s[r][c] = v;
    }
    __syncthreads();

    float dofx = sc[0], dofy = sc[1], cossin = sc[2], bsin = sc[3], asin_ = sc[4];

    // Normalized separable gaussian weights g(a)=exp(-a^2/50)/S.
    float e1 = __expf(-0.02f), e2 = __expf(-0.08f);
    float invs = 1.f / (1.f + 2.f*(e1 + e2));
    float w0 = e2*invs, w1 = e1*invs, w2 = invs;

    // Gaussian column pass: t_s[r][c] = sum_b w[b] * u(i0+r-2, j0+c+b)
    for (int idx = tid; idx < 36*32; idx += 256) {
        int r = idx >> 5, c = idx & 31;
        t_s[r][c] = w0*(u_s[r][c] + u_s[r][c+4])
                  + w1*(u_s[r][c+1] + u_s[r][c+3])
                  + w2* u_s[r][c+2];
    }

    // q_new over tile + halo 1. Outside-image positions contribute 0 to the
    // divergence (zero-padded conv), so store zeros there.
    for (int idx = tid; idx < 34*34; idx += 256) {
        int r = idx / 34, c = idx - r*34;
        int gi = i0 + r - 1, gj = j0 + c - 1;
        float txqv = 0.f, tyqv = 0.f, qnv = 0.f;
        if ((unsigned)gi < HH && (unsigned)gj < WW) {
            float uc  = u_s[r+1][c+1];
            float un0 = u_s[r+2][c+1] - uc;      // u(i+1,j) - u(i,j)
            float un1 = u_s[r+1][c+2] - uc;      // u(i,j+1) - u(i,j)
            float dxv = (float)(gi+1) - CC - dofx;
            float dyv = (float)(gj+1) - CC - dofy;
            float Tx = dyv*bsin   - dxv*cossin;
            float Ty = dyv*cossin - dxv*asin_;
            float tn = sqrtf(Tx*Tx + Ty*Ty) + 1e-10f;
            float inv = __fdividef(1.f, tn);
            Tx *= inv; Ty *= inv;
            qnv  = q_in[gi*WW + gj] - (un0*Tx + un1*Ty);   // TAU = 1
            txqv = Tx*qnv; tyqv = Ty*qnv;
        }
        txq_s[r][c] = txqv; tyq_s[r][c] = tyqv; qn_s[r][c] = qnv;
    }
    __syncthreads();

    float acc[6] = {0,0,0,0,0,0};
    bool wout = (out != nullptr);
#pragma unroll
    for (int k = 0; k < 4; k++) {
        int i = threadIdx.y + k*8;
        int j = threadIdx.x;
        int gi = i0 + i, gj = j0 + j;
        int gidx = gi*WW + gj;

        // divergence: A(i,j)-A(i-1,j) + B(i,j)-B(i,j-1)
        float Tq = txq_s[i+1][j+1] - txq_s[i][j+1]
                 + tyq_s[i+1][j+1] - tyq_s[i+1][j];

        // gaussian row pass
        float conv = w0*(t_s[i][j] + t_s[i+4][j])
                   + w1*(t_s[i+1][j] + t_s[i+3][j])
                   + w2* t_s[i+2][j];

        // p = conv(1-2u) = (in-bounds kernel mass) - 2*conv(u)
        float ra = 1.f, rb = 1.f;
        if (gi == 0) ra -= w0 + w1; else if (gi == 1) ra -= w0;
        if (gi == HH-1) ra -= w0 + w1; else if (gi == HH-2) ra -= w0;
        if (gj == 0) rb -= w0 + w1; else if (gj == 1) rb -= w0;
        if (gj == WW-1) rb -= w0 + w1; else if (gj == WW-2) rb -= w0;

        float p   = ra*rb - 2.f*conv;
        float arg = ob[gidx] - p - Tq;          // LAM = EPS = 1
        float un  = 1.f/(1.f + __expf(-arg));
        u_out[gidx] = un;
        q_out[gidx] = qn_s[i+1][j+1];
        if (wout) out[(size_t)b*NPIX + gidx] = arg;

        float xc = (float)(gi+1) - CC, yc = (float)(gj+1) - CC;
        acc[0]+=un; float a1=un*xc, a2=un*yc;
        acc[1]+=a1; acc[2]+=a2; acc[3]+=a1*xc; acc[4]+=a2*yc; acc[5]+=a1*yc;
    }

    moments_accum_and_atomic(acc, g_sums[(t+1)%3][b], red);
}

extern "C" void kernel_launch(void* const* d_in, const int* in_sizes, int n_in,
                              void* d_out, int out_size) {
    const float* o = (const float*)d_in[0];
    float* out = (float*)d_out;
    (void)in_sizes; (void)n_in; (void)out_size;

    dim3 grid(WW/32, HH/32, BB);
    dim3 blk(32, 8);

    zero_sums_kernel<<<1, 256>>>();
    init_kernel<<<grid, blk>>>(o);
    for (int t = 0; t < ITERS; t++)
        step_kernel<<<grid, blk>>>(o, (t == ITERS-1) ? out : nullptr, t);
}

// round 7
// speedup vs baseline: 1.5167x; 1.5167x over previous
#include <cuda_runtime.h>

#define HH 512
#define WW 512
#define BB 8
#define NPIX (HH*WW)
#define ITERS 50
#define CC 256.5f

// Double-buffered state + triple-buffered moment sums (zero/accum/read rotate).
__device__ float  g_u[2][BB*NPIX];
__device__ float  g_q[2][BB*NPIX];
__device__ double g_sums[3][BB][8];

__global__ void zero_sums_kernel() {
    int i = threadIdx.x;
    if (i < 3*BB*8) reinterpret_cast<double*>(g_sums)[i] = 0.0;
}

__device__ __forceinline__ void moments_reduce(float acc[6], double* dst,
                                               float (*red)[6], int tid) {
    int lane = tid & 31, wp = tid >> 5;
#pragma unroll
    for (int off = 16; off; off >>= 1)
#pragma unroll
        for (int k = 0; k < 6; k++) acc[k] += __shfl_xor_sync(0xffffffffu, acc[k], off);
    if (lane == 0)
#pragma unroll
        for (int k = 0; k < 6; k++) red[wp][k] = acc[k];
    __syncthreads();
    if (tid == 0) {
#pragma unroll
        for (int k = 0; k < 6; k++) {
            float s = red[0][k];
#pragma unroll
            for (int w = 1; w < 8; w++) s += red[w][k];
            atomicAdd(&dst[k], (double)s);
        }
    }
}

// u0 = sigmoid(o), q0 = 0, moments(u0) -> g_sums[0]. 4 px / thread, float4 I/O.
__global__ __launch_bounds__(256) void init_kernel(const float* __restrict__ o) {
    int tid = threadIdx.x;
    int b  = blockIdx.z;
    int i0 = blockIdx.y * 32, j0 = blockIdx.x * 32;
    int i = tid >> 3, j = (tid & 7) * 4;
    int gi = i0 + i, gj = j0 + j;
    int gidx = gi*WW + gj;
    const float* ob = o + (size_t)b * NPIX;

    float4 ov = *(const float4*)(ob + gidx);
    float un[4];
    un[0] = 1.f/(1.f+__expf(-ov.x));
    un[1] = 1.f/(1.f+__expf(-ov.y));
    un[2] = 1.f/(1.f+__expf(-ov.z));
    un[3] = 1.f/(1.f+__expf(-ov.w));
    *(float4*)(g_u[0] + (size_t)b*NPIX + gidx) = make_float4(un[0],un[1],un[2],un[3]);
    *(float4*)(g_q[0] + (size_t)b*NPIX + gidx) = make_float4(0.f,0.f,0.f,0.f);

    float xc = (float)(gi+1) - CC;
    float s0 = 0.f, sy = 0.f, syy = 0.f;
#pragma unroll
    for (int k = 0; k < 4; k++) {
        float yc = (float)(gj+k+1) - CC;
        s0 += un[k]; sy += un[k]*yc; syy += un[k]*yc*yc;
    }
    float acc[6] = { s0, xc*s0, sy, xc*xc*s0, syy, xc*sy };
    __shared__ float red[8][6];
    moments_reduce(acc, g_sums[0][b], red, tid);
}

// One full iteration, fully float4-vectorized: separable 5x5 gaussian, Tx/Ty,
// q update, Tq divergence, u update, next iteration's moments.
__global__ __launch_bounds__(256, 5) void step_kernel(const float* __restrict__ o,
                                                      float* __restrict__ out, int t)
{
    __shared__ float u_s[36][40];    // u tile rows i0-2..i0+33, cols j0-4..j0+35 (0-pad OOB)
    __shared__ float q_s[34][40];    // q tile rows i0-1..i0+32, same cols
    __shared__ float t_s[36][36];    // gaussian column pass (cols 0..31 used)
    __shared__ float txq_s[33][36];  // Tx*q_new, rows i0-1..i0+31, cols j0-2..j0+33
    __shared__ float tyq_s[33][36];
    __shared__ float qn_s[33][36];
    __shared__ float sc[5];
    __shared__ float red[8][6];

    int tid = threadIdx.x;
    int b  = blockIdx.z;
    int i0 = blockIdx.y * 32, j0 = blockIdx.x * 32;

    const float* u_in  = g_u[t & 1]     + (size_t)b * NPIX;
    const float* q_in  = g_q[t & 1]     + (size_t)b * NPIX;
    float*       u_out = g_u[(t+1) & 1] + (size_t)b * NPIX;
    float*       q_out = g_q[(t+1) & 1] + (size_t)b * NPIX;
    const float* ob    = o              + (size_t)b * NPIX;

    // Zero the sums buffer used two iterations from now.
    if (blockIdx.x == 0 && blockIdx.y == 0 && b == 0 && tid < BB*8)
        reinterpret_cast<double*>(g_sums[(t+2)%3])[tid] = 0.0;

    if (tid == 0) {  // scalars from fp64 moments (centered at CC)
        const double* S = g_sums[t % 3][b];
        double inv = 1.0 / S[0];
        double dx = S[1]*inv, dy = S[2]*inv;
        sc[0] = (float)dx; sc[1] = (float)dy;
        sc[2] = (float)(S[5]*inv - dx*dy);   // cossin
        sc[3] = (float)(S[3]*inv - dx*dx);   // bsin
        sc[4] = (float)(S[4]*inv - dy*dy);   // asin
    }

    // ---- Phase A: vectorized tile loads (u: 36x10 vec4, q: 34x10 vec4) ----
    for (int idx = tid; idx < 700; idx += 256) {
        bool isq = idx >= 360;
        int k = isq ? idx - 360 : idx;
        int r = k / 10, c = k - r*10;
        int gi = i0 + r - (isq ? 1 : 2);
        int gj = j0 + 4*c - 4;
        float4 v = make_float4(0.f,0.f,0.f,0.f);
        if ((unsigned)gi < HH && (unsigned)gj < WW)
            v = *(const float4*)((isq ? q_in : u_in) + gi*WW + gj);
        if (isq) *(float4*)&q_s[r][4*c] = v;
        else     *(float4*)&u_s[r][4*c] = v;
    }
    __syncthreads();

    float dofx = sc[0], dofy = sc[1], cossin = sc[2], bsin = sc[3], asin_ = sc[4];

    // Normalized separable gaussian weights g(a)=exp(-a^2/50)/S.
    float e1 = __expf(-0.02f), e2 = __expf(-0.08f);
    float invs = 1.f / (1.f + 2.f*(e1 + e2));
    float w0 = e2*invs, w1 = e1*invs, w2 = invs;

    // ---- Phase B: gaussian column pass, 36 rows x 8 vec4 groups ----
    for (int idx = tid; idx < 288; idx += 256) {
        int r = idx >> 3, x = idx & 7;
        int g0 = 4*x;
        float4 a = *(float4*)&u_s[r][g0];
        float4 bb = *(float4*)&u_s[r][g0+4];
        float4 cc = *(float4*)&u_s[r][g0+8];
        float e[12] = {a.x,a.y,a.z,a.w, bb.x,bb.y,bb.z,bb.w, cc.x,cc.y,cc.z,cc.w};
        float4 ot;
        ot.x = w0*(e[2]+e[6]) + w1*(e[3]+e[5]) + w2*e[4];
        ot.y = w0*(e[3]+e[7]) + w1*(e[4]+e[6]) + w2*e[5];
        ot.z = w0*(e[4]+e[8]) + w1*(e[5]+e[7]) + w2*e[6];
        ot.w = w0*(e[5]+e[9]) + w1*(e[6]+e[8]) + w2*e[7];
        *(float4*)&t_s[r][g0] = ot;
    }

    // ---- Phase C: q_new / Tx*q / Ty*q over halo-1 region, 33 rows x 9 vec4 ----
    for (int idx = tid; idx < 297; idx += 256) {
        int r = idx / 9, c = idx - r*9;
        int m0 = 4*c;
        int gi = i0 - 1 + r;                 // row of these 4 pixels
        float4 ca = *(float4*)&u_s[r+1][m0];
        float4 cb = *(float4*)&u_s[r+1][m0+4];
        float4 da = *(float4*)&u_s[r+2][m0];
        float4 db = *(float4*)&u_s[r+2][m0+4];
        float4 qa = *(float4*)&q_s[r][m0];
        float4 qb = *(float4*)&q_s[r][m0+4];
        float uc[4] = {ca.z, ca.w, cb.x, cb.y};   // u(i,j)
        float ur[4] = {ca.w, cb.x, cb.y, cb.z};   // u(i,j+1)
        float ud[4] = {da.z, da.w, db.x, db.y};   // u(i+1,j)
        float qq[4] = {qa.z, qa.w, qb.x, qb.y};
        float dxv = (float)(gi+1) - CC - dofx;
        bool rowok = (gi >= 0);
        float rtx[4], rty[4], rqn[4];
#pragma unroll
        for (int k = 0; k < 4; k++) {
            int gj = j0 + m0 + k - 2;
            float dyv = (float)(gj+1) - CC - dofy;
            float Tx = dyv*bsin   - dxv*cossin;
            float Ty = dyv*cossin - dxv*asin_;
            float inv = rsqrtf(fmaf(Tx, Tx, Ty*Ty) + 1e-20f);
            float nx = Tx*inv, ny = Ty*inv;
            float qn = qq[k] - ((ud[k]-uc[k])*nx + (ur[k]-uc[k])*ny);  // TAU=1
            bool ok = rowok && ((unsigned)gj < WW);
            qn = ok ? qn : 0.f;
            rqn[k] = qn; rtx[k] = nx*qn; rty[k] = ny*qn;
        }
        *(float4*)&txq_s[r][m0] = make_float4(rtx[0],rtx[1],rtx[2],rtx[3]);
        *(float4*)&tyq_s[r][m0] = make_float4(rty[0],rty[1],rty[2],rty[3]);
        *(float4*)&qn_s [r][m0] = make_float4(rqn[0],rqn[1],rqn[2],rqn[3]);
    }
    __syncthreads();

    // ---- Phase D: output, 1 vec4 strip per thread ----
    int i = tid >> 3, j = (tid & 7) * 4;
    int gi = i0 + i, gj0 = j0 + j;
    int gidx = gi*WW + gj0;

    float4 t0 = *(float4*)&t_s[i  ][j];
    float4 t1 = *(float4*)&t_s[i+1][j];
    float4 t2 = *(float4*)&t_s[i+2][j];
    float4 t3 = *(float4*)&t_s[i+3][j];
    float4 t4 = *(float4*)&t_s[i+4][j];
    float ta[4] = {t0.x,t0.y,t0.z,t0.w};
    float tb[4] = {t1.x,t1.y,t1.z,t1.w};
    float tc[4] = {t2.x,t2.y,t2.z,t2.w};
    float td[4] = {t3.x,t3.y,t3.z,t3.w};
    float te[4] = {t4.x,t4.y,t4.z,t4.w};

    float4 A0 = *(float4*)&txq_s[i+1][j], A1 = *(float4*)&txq_s[i+1][j+4];
    float4 B0 = *(float4*)&txq_s[i  ][j], B1 = *(float4*)&txq_s[i  ][j+4];
    float4 Y0 = *(float4*)&tyq_s[i+1][j], Y1 = *(float4*)&tyq_s[i+1][j+4];
    float4 Q0 = *(float4*)&qn_s [i+1][j], Q1 = *(float4*)&qn_s [i+1][j+4];
    float ax[8] = {A0.x,A0.y,A0.z,A0.w, A1.x,A1.y,A1.z,A1.w};
    float bx[8] = {B0.x,B0.y,B0.z,B0.w, B1.x,B1.y,B1.z,B1.w};
    float yx[8] = {Y0.x,Y0.y,Y0.z,Y0.w, Y1.x,Y1.y,Y1.z,Y1.w};
    float qx[8] = {Q0.x,Q0.y,Q0.z,Q0.w, Q1.x,Q1.y,Q1.z,Q1.w};

    float4 ov = *(const float4*)(ob + gidx);
    float oo[4] = {ov.x, ov.y, ov.z, ov.w};

    // row border mass for p = conv(1-2u)
    float ra = 1.f;
    if (gi == 0) ra -= w0 + w1; else if (gi == 1) ra -= w0;
    if (gi == HH-1) ra -= w0 + w1; else if (gi == HH-2) ra -= w0;

    float xc = (float)(gi+1) - CC;
    float s0 = 0.f, sy = 0.f, syy = 0.f;
    float uo[4], ao[4];
    bool wout = (out != nullptr);
#pragma unroll
    for (int k = 0; k < 4; k++) {
        int gj = gj0 + k;
        float Tq = ax[k+2] - bx[k+2] + yx[k+2] - yx[k+1];
        float conv = w0*(ta[k]+te[k]) + w1*(tb[k]+td[k]) + w2*tc[k];
        float rb = 1.f;
        if (gj == 0) rb -= w0 + w1; else if (gj == 1) rb -= w0;
        if (gj == WW-1) rb -= w0 + w1; else if (gj == WW-2) rb -= w0;
        float p   = ra*rb - 2.f*conv;
        float arg = oo[k] - p - Tq;          // LAM = EPS = 1
        float un  = 1.f/(1.f + __expf(-arg));
        uo[k] = un; ao[k] = arg;
        float yc = (float)(gj+1) - CC;
        s0 += un; sy += un*yc; syy += un*yc*yc;
    }
    *(float4*)(u_out + gidx) = make_float4(uo[0],uo[1],uo[2],uo[3]);
    *(float4*)(q_out + gidx) = make_float4(qx[2],qx[3],qx[4],qx[5]);
    if (wout)
        *(float4*)(out + (size_t)b*NPIX + gidx) = make_float4(ao[0],ao[1],ao[2],ao[3]);

    float acc[6] = { s0, xc*s0, sy, xc*xc*s0, syy, xc*sy };
    moments_reduce(acc, g_sums[(t+1)%3][b], red, tid);
}

extern "C" void kernel_launch(void* const* d_in, const int* in_sizes, int n_in,
                              void* d_out, int out_size) {
    const float* o = (const float*)d_in[0];
    float* out = (float*)d_out;
    (void)in_sizes; (void)n_in; (void)out_size;

    dim3 grid(WW/32, HH/32, BB);

    zero_sums_kernel<<<1, 256>>>();
    init_kernel<<<grid, 256>>>(o);
    for (int t = 0; t < ITERS; t++)
        step_kernel<<<grid, 256>>>(o, (t == ITERS-1) ? out : nullptr, t);
}

// round 9
// speedup vs baseline: 1.6827x; 1.1095x over previous
#include <cuda_runtime.h>

#define HH 512
#define WW 512
#define BB 8
#define NPIX (HH*WW)
#define ITERS 50
#define CC 256.5f

// Double-buffered state + triple-buffered moment sums (zero/accum/read rotate).
__device__ float  g_u[2][BB*NPIX];
__device__ float  g_q[2][BB*NPIX];
__device__ double g_sums[3][BB][8];

__global__ void zero_sums_kernel() {
    int i = threadIdx.x;
    if (i < 3*BB*8) reinterpret_cast<double*>(g_sums)[i] = 0.0;
}

__device__ __forceinline__ float sigmoid_fast(float x) {
    float t;
    asm("tanh.approx.f32 %0, %1;" : "=f"(t) : "f"(0.5f * x));
    return fmaf(0.5f, t, 0.5f);
}

// Two-stage moment reduction. Threads are laid out tid = row*8 + colgroup, so
// the 8 lanes of a row share xc: reduce (s0,sy,syy) over them (9 SHFL), park
// row triples in smem, warp 0 folds in xc and finishes (amortized ~free).
__device__ __forceinline__ void moments3_reduce(float s0, float sy, float syy,
                                                int i0, double* dst,
                                                float (*rowred)[3], int tid) {
#pragma unroll
    for (int off = 1; off <= 4; off <<= 1) {
        s0  += __shfl_xor_sync(0xffffffffu, s0,  off);
        sy  += __shfl_xor_sync(0xffffffffu, sy,  off);
        syy += __shfl_xor_sync(0xffffffffu, syy, off);
    }
    if ((tid & 7) == 0) {
        int r = tid >> 3;
        rowred[r][0] = s0; rowred[r][1] = sy; rowred[r][2] = syy;
    }
    __syncthreads();
    if (tid < 32) {
        float a0 = rowred[tid][0], a1 = rowred[tid][1], a2 = rowred[tid][2];
        float xc = (float)(i0 + tid + 1) - CC;
        float m[6] = { a0, xc*a0, a1, xc*xc*a0, a2, xc*a1 };
#pragma unroll
        for (int off = 16; off; off >>= 1)
#pragma unroll
            for (int k = 0; k < 6; k++) m[k] += __shfl_xor_sync(0xffffffffu, m[k], off);
        if (tid == 0)
#pragma unroll
            for (int k = 0; k < 6; k++) atomicAdd(&dst[k], (double)m[k]);
    }
}

// u0 = sigmoid(o), q0 = 0, moments(u0) -> g_sums[0]. 4 px / thread, float4 I/O.
__global__ __launch_bounds__(256) void init_kernel(const float* __restrict__ o) {
    int tid = threadIdx.x;
    int b  = blockIdx.z;
    int i0 = blockIdx.y * 32, j0 = blockIdx.x * 32;
    int i = tid >> 3, j = (tid & 7) * 4;
    int gi = i0 + i, gj = j0 + j;
    int gidx = gi*WW + gj;
    const float* ob = o + (size_t)b * NPIX;

    float4 ov = *(const float4*)(ob + gidx);
    float un[4];
    un[0] = sigmoid_fast(ov.x);
    un[1] = sigmoid_fast(ov.y);
    un[2] = sigmoid_fast(ov.z);
    un[3] = sigmoid_fast(ov.w);
    *(float4*)(g_u[0] + (size_t)b*NPIX + gidx) = make_float4(un[0],un[1],un[2],un[3]);
    *(float4*)(g_q[0] + (size_t)b*NPIX + gidx) = make_float4(0.f,0.f,0.f,0.f);

    float s0 = 0.f, sy = 0.f, syy = 0.f;
#pragma unroll
    for (int k = 0; k < 4; k++) {
        float yc = (float)(gj+k+1) - CC;
        s0 += un[k]; sy += un[k]*yc; syy += un[k]*yc*yc;
    }
    __shared__ float rowred[32][3];
    moments3_reduce(s0, sy, syy, i0, g_sums[0][b], rowred, tid);
}

// One full iteration: separable 5x5 gaussian (p), Tx/Ty, q update (stored
// straight to global), Tq divergence, u update, next iteration's moments.
__global__ __launch_bounds__(256, 5) void step_kernel(const float* __restrict__ o,
                                                      float* __restrict__ out, int t)
{
    __shared__ float u_s[36][40];    // u tile rows i0-2..i0+33, cols j0-4..j0+35 (0-pad OOB)
    __shared__ float q_s[34][40];    // q tile rows i0-1..i0+32, same cols
    __shared__ float t_s[36][36];    // gaussian column pass (cols 0..31 used)
    __shared__ float txq_s[33][36];  // Tx*q_new, rows i0-1..i0+31, cols j0-2..j0+33
    __shared__ float tyq_s[33][36];
    __shared__ float sc[5];
    __shared__ float rowred[32][3];

    int tid = threadIdx.x;
    int b  = blockIdx.z;
    int i0 = blockIdx.y * 32, j0 = blockIdx.x * 32;

    const float* u_in  = g_u[t & 1]     + (size_t)b * NPIX;
    const float* q_in  = g_q[t & 1]     + (size_t)b * NPIX;
    float*       u_out = g_u[(t+1) & 1] + (size_t)b * NPIX;
    float*       q_out = g_q[(t+1) & 1] + (size_t)b * NPIX;
    const float* ob    = o              + (size_t)b * NPIX;

    // Output strip coords (also used to prefetch o before the first sync).
    int di = tid >> 3, dj = (tid & 7) * 4;
    int dgi = i0 + di, dgj0 = j0 + dj;
    int dgidx = dgi*WW + dgj0;
    float4 ov = *(const float4*)(ob + dgidx);   // prefetch: independent of smem

    // Zero the sums buffer used two iterations from now.
    if (blockIdx.x == 0 && blockIdx.y == 0 && b == 0 && tid < BB*8)
        reinterpret_cast<double*>(g_sums[(t+2)%3])[tid] = 0.0;

    if (tid == 0) {  // scalars from fp64 moments (centered at CC)
        const double* S = g_sums[t % 3][b];
        double inv = 1.0 / S[0];
        double dx = S[1]*inv, dy = S[2]*inv;
        sc[0] = (float)dx; sc[1] = (float)dy;
        sc[2] = (float)(S[5]*inv - dx*dy);   // cossin
        sc[3] = (float)(S[3]*inv - dx*dx);   // bsin
        sc[4] = (float)(S[4]*inv - dy*dy);   // asin
    }

    // ---- Phase A: vectorized tile loads (u: 36x10 vec4, q: 34x10 vec4) ----
#pragma unroll
    for (int s = 0; s < 3; s++) {
        int idx = tid + 256*s;
        if (idx < 700) {
            bool isq = idx >= 360;
            int k = isq ? idx - 360 : idx;
            int r = k / 10, c = k - r*10;
            int gi = i0 + r - (isq ? 1 : 2);
            int gj = j0 + 4*c - 4;
            float4 v = make_float4(0.f,0.f,0.f,0.f);
            if ((unsigned)gi < HH && (unsigned)gj < WW)
                v = *(const float4*)((isq ? q_in : u_in) + gi*WW + gj);
            if (isq) *(float4*)&q_s[r][4*c] = v;
            else     *(float4*)&u_s[r][4*c] = v;
        }
    }
    __syncthreads();

    float dofx = sc[0], dofy = sc[1], cossin = sc[2], bsin = sc[3], asin_ = sc[4];

    // Normalized separable gaussian weights g(a)=exp(-a^2/50)/S.
    float e1 = __expf(-0.02f), e2 = __expf(-0.08f);
    float invs = 1.f / (1.f + 2.f*(e1 + e2));
    float w0 = e2*invs, w1 = e1*invs, w2 = invs;

    // ---- Phase B: gaussian column pass, 36 rows x 8 vec4 groups ----
#pragma unroll
    for (int s = 0; s < 2; s++) {
        int idx = tid + 256*s;
        if (idx < 288) {
            int r = idx >> 3, x = idx & 7;
            int g0 = 4*x;
            float4 a = *(float4*)&u_s[r][g0];
            float4 bb = *(float4*)&u_s[r][g0+4];
            float4 cc = *(float4*)&u_s[r][g0+8];
            float e[12] = {a.x,a.y,a.z,a.w, bb.x,bb.y,bb.z,bb.w, cc.x,cc.y,cc.z,cc.w};
            float4 ot;
            ot.x = w0*(e[2]+e[6]) + w1*(e[3]+e[5]) + w2*e[4];
            ot.y = w0*(e[3]+e[7]) + w1*(e[4]+e[6]) + w2*e[5];
            ot.z = w0*(e[4]+e[8]) + w1*(e[5]+e[7]) + w2*e[6];
            ot.w = w0*(e[5]+e[9]) + w1*(e[6]+e[8]) + w2*e[7];
            *(float4*)&t_s[r][g0] = ot;
        }
    }

    // ---- Phase C: q_new / Tx*q / Ty*q over halo-1 region (33 rows x 9 vec4).
    // q_new for in-tile pixels goes straight to q_out (no staging tile).
#pragma unroll
    for (int s = 0; s < 2; s++) {
        int idx = tid + 256*s;
        if (idx < 297) {
            int r = idx / 9, c = idx - r*9;
            int m0 = 4*c;
            int gi = i0 - 1 + r;
            float4 ca = *(float4*)&u_s[r+1][m0];
            float4 cb = *(float4*)&u_s[r+1][m0+4];
            float4 da = *(float4*)&u_s[r+2][m0];
            float4 db = *(float4*)&u_s[r+2][m0+4];
            float4 qa = *(float4*)&q_s[r][m0];
            float4 qb = *(float4*)&q_s[r][m0+4];
            float uc[4] = {ca.z, ca.w, cb.x, cb.y};   // u(i,j)
            float ur[4] = {ca.w, cb.x, cb.y, cb.z};   // u(i,j+1)
            float ud[4] = {da.z, da.w, db.x, db.y};   // u(i+1,j)
            float qq[4] = {qa.z, qa.w, qb.x, qb.y};
            float dxv = (float)(gi+1) - CC - dofx;
            bool rowok = (gi >= 0);
            float rtx[4], rty[4], rqn[4];
#pragma unroll
            for (int k = 0; k < 4; k++) {
                int gj = j0 + m0 + k - 2;
                float dyv = (float)(gj+1) - CC - dofy;
                float Tx = dyv*bsin   - dxv*cossin;
                float Ty = dyv*cossin - dxv*asin_;
                float inv = rsqrtf(fmaf(Tx, Tx, Ty*Ty) + 1e-20f);
                float nx = Tx*inv, ny = Ty*inv;
                float qn = qq[k] - ((ud[k]-uc[k])*nx + (ur[k]-uc[k])*ny);  // TAU=1
                bool ok = rowok && ((unsigned)gj < WW);
                qn = ok ? qn : 0.f;
                rqn[k] = qn; rtx[k] = nx*qn; rty[k] = ny*qn;
            }
            *(float4*)&txq_s[r][m0] = make_float4(rtx[0],rtx[1],rtx[2],rtx[3]);
            *(float4*)&tyq_s[r][m0] = make_float4(rty[0],rty[1],rty[2],rty[3]);
            if (r >= 1) {
#pragma unroll
                for (int k = 0; k < 4; k++) {
                    int lj = m0 + k - 2;
                    if ((unsigned)lj < 32u) q_out[gi*WW + j0 + lj] = rqn[k];
                }
            }
        }
    }
    __syncthreads();

    // ---- Phase D: output, 1 vec4 strip per thread ----
    int i = di, j = dj;
    float4 t0 = *(float4*)&t_s[i  ][j];
    float4 t1 = *(float4*)&t_s[i+1][j];
    float4 t2 = *(float4*)&t_s[i+2][j];
    float4 t3 = *(float4*)&t_s[i+3][j];
    float4 t4 = *(float4*)&t_s[i+4][j];
    float ta[4] = {t0.x,t0.y,t0.z,t0.w};
    float tb[4] = {t1.x,t1.y,t1.z,t1.w};
    float tc[4] = {t2.x,t2.y,t2.z,t2.w};
    float td[4] = {t3.x,t3.y,t3.z,t3.w};
    float te[4] = {t4.x,t4.y,t4.z,t4.w};

    float4 A0 = *(float4*)&txq_s[i+1][j], A1 = *(float4*)&txq_s[i+1][j+4];
    float4 B0 = *(float4*)&txq_s[i  ][j], B1 = *(float4*)&txq_s[i  ][j+4];
    float4 Y0 = *(float4*)&tyq_s[i+1][j], Y1 = *(float4*)&tyq_s[i+1][j+4];
    float ax[8] = {A0.x,A0.y,A0.z,A0.w, A1.x,A1.y,A1.z,A1.w};
    float bx[8] = {B0.x,B0.y,B0.z,B0.w, B1.x,B1.y,B1.z,B1.w};
    float yx[8] = {Y0.x,Y0.y,Y0.z,Y0.w, Y1.x,Y1.y,Y1.z,Y1.w};

    float oo[4] = {ov.x, ov.y, ov.z, ov.w};

    // row border mass for p = conv(1-2u)
    float ra = 1.f;
    if (dgi == 0) ra -= w0 + w1; else if (dgi == 1) ra -= w0;
    if (dgi == HH-1) ra -= w0 + w1; else if (dgi == HH-2) ra -= w0;

    float s0 = 0.f, sy = 0.f, syy = 0.f;
    float uo[4], ao[4];
    bool wout = (out != nullptr);
#pragma unroll
    for (int k = 0; k < 4; k++) {
        int gj = dgj0 + k;
        float Tq = ax[k+2] - bx[k+2] + yx[k+2] - yx[k+1];
        float conv = w0*(ta[k]+te[k]) + w1*(tb[k]+td[k]) + w2*tc[k];
        float rb = 1.f;
        if (gj == 0) rb -= w0 + w1; else if (gj == 1) rb -= w0;
        if (gj == WW-1) rb -= w0 + w1; else if (gj == WW-2) rb -= w0;
        float p   = ra*rb - 2.f*conv;
        float arg = oo[k] - p - Tq;          // LAM = EPS = 1
        float un  = sigmoid_fast(arg);
        uo[k] = un; ao[k] = arg;
        float yc = (float)(gj+1) - CC;
        s0 += un; sy += un*yc; syy += un*yc*yc;
    }
    *(float4*)(u_out + dgidx) = make_float4(uo[0],uo[1],uo[2],uo[3]);
    if (wout)
        *(float4*)(out + (size_t)b*NPIX + dgidx) = make_float4(ao[0],ao[1],ao[2],ao[3]);

    moments3_reduce(s0, sy, syy, i0, g_sums[(t+1)%3][b], rowred, tid);
}

extern "C" void kernel_launch(void* const* d_in, const int* in_sizes, int n_in,
                              void* d_out, int out_size) {
    const float* o = (const float*)d_in[0];
    float* out = (float*)d_out;
    (void)in_sizes; (void)n_in; (void)out_size;

    dim3 grid(WW/32, HH/32, BB);

    zero_sums_kernel<<<1, 256>>>();
    init_kernel<<<grid, 256>>>(o);
    for (int t = 0; t < ITERS; t++)
        step_kernel<<<grid, 256>>>(o, (t == ITERS-1) ? out : nullptr, t);
}